// round 2
// baseline (speedup 1.0000x reference)
#include <cuda_runtime.h>
#include <cuda_bf16.h>

#define N_NODES 40000
#define N_EDGES 480000
#define NPLANE  (N_NODES * 64)

__device__ __align__(16) float g_hs[N_NODES * 64];
__device__ __align__(16) float g_hv[3 * N_NODES * 64];
__device__ __align__(16) float g_sc[N_NODES * 320];
__device__ __align__(16) float g_agg[(size_t)N_NODES * 512];

__device__ __forceinline__ float swishf(float x) {
    return x / (1.0f + __expf(-x));
}

typedef unsigned long long u64;

__device__ __forceinline__ u64 pack2(float lo, float hi) {
    u64 r; asm("mov.b64 %0, {%1, %2};" : "=l"(r) : "f"(lo), "f"(hi)); return r;
}
__device__ __forceinline__ float2 unpack2(u64 v) {
    float2 r; asm("mov.b64 {%0, %1}, %2;" : "=f"(r.x), "=f"(r.y) : "l"(v)); return r;
}
__device__ __forceinline__ void ffma2(u64& d, u64 a, u64 b) {
    asm("fma.rn.f32x2 %0, %1, %2, %0;" : "+l"(d) : "l"(a), "l"(b));
}

#define INV8F   0.3535533905932738f
#define INV64F  0.125f
#define INV128F 0.08838834764831845f
#define INVNN   0.28867513459481287f
#define SQRT3F  1.7320508075688772f
#define SQRT2F  1.4142135623730951f
#define PI_F    3.14159265358979323846f

// =====================================================================
// Kernel 1: node "up" linear + species skip. Warp handles 2 nodes.
// 8 warps/block -> 16 nodes/block.
// =====================================================================
__global__ void __launch_bounds__(256) k_node_up(
    const float* __restrict__ ns, const float* __restrict__ nv,
    const int* __restrict__ specie,
    const float* __restrict__ Wus, const float* __restrict__ Wuv,
    const float* __restrict__ Wss, const float* __restrict__ Wsv)
{
    __shared__ __align__(16) float xs[8][2][64];
    __shared__ __align__(16) float xv[8][2][192];
    int w = threadIdx.x >> 5, t = threadIdx.x & 31;
    int n0 = (blockIdx.x * 8 + w) * 2;

#pragma unroll
    for (int nl = 0; nl < 2; nl++) {
        int n = n0 + nl;
        xs[w][nl][t]      = __ldg(ns + n * 64 + t);
        xs[w][nl][t + 32] = __ldg(ns + n * 64 + t + 32);
#pragma unroll
        for (int q = 0; q < 6; q++)
            xv[w][nl][t + 32 * q] = __ldg(nv + n * 192 + t + 32 * q);
    }
    __syncwarp();

    // ---- up-part: weights shared between the two nodes ----
    {
        float A[2][2] = {{0,0},{0,0}};
        float B[2][2][3] = {};
#pragma unroll 4
        for (int i = 0; i < 64; i++) {
            float ws0 = __ldg(Wus + i * 64 + t);
            float ws1 = __ldg(Wus + i * 64 + t + 32);
            float wv0 = __ldg(Wuv + i * 64 + t);
            float wv1 = __ldg(Wuv + i * 64 + t + 32);
#pragma unroll
            for (int nl = 0; nl < 2; nl++) {
                float x = xs[w][nl][i];
                A[nl][0] += x * ws0; A[nl][1] += x * ws1;
                float v0 = xv[w][nl][i * 3 + 0];
                float v1 = xv[w][nl][i * 3 + 1];
                float v2 = xv[w][nl][i * 3 + 2];
                B[nl][0][0] += v0 * wv0; B[nl][0][1] += v1 * wv0; B[nl][0][2] += v2 * wv0;
                B[nl][1][0] += v0 * wv1; B[nl][1][1] += v1 * wv1; B[nl][1][2] += v2 * wv1;
            }
        }
#pragma unroll
        for (int nl = 0; nl < 2; nl++) {
            int n = n0 + nl;
            g_hs[n * 64 + t]      = A[nl][0] * INV64F;
            g_hs[n * 64 + t + 32] = A[nl][1] * INV64F;
#pragma unroll
            for (int c = 0; c < 3; c++) {
                g_hv[c * NPLANE + n * 64 + t]      = B[nl][0][c] * INV64F;
                g_hv[c * NPLANE + n * 64 + t + 32] = B[nl][1][c] * INV64F;
            }
        }
    }

    // ---- skip-part: species-indexed weights (distinct per node) ----
    {
        int sp0 = __ldg(specie + n0), sp1 = __ldg(specie + n0 + 1);
        const float* Ws[2] = { Wss + sp0 * 64 * 128, Wss + sp1 * 64 * 128 };
        const float* Wv[2] = { Wsv + sp0 * 64 * 64,  Wsv + sp1 * 64 * 64 };
        float S[2][4] = {};
        float C[2][2][3] = {};
#pragma unroll 2
        for (int i = 0; i < 64; i++) {
#pragma unroll
            for (int nl = 0; nl < 2; nl++) {
                float x = xs[w][nl][i];
#pragma unroll
                for (int q = 0; q < 4; q++)
                    S[nl][q] += x * __ldg(Ws[nl] + i * 128 + t + 32 * q);
                float w0 = __ldg(Wv[nl] + i * 64 + t);
                float w1 = __ldg(Wv[nl] + i * 64 + t + 32);
                float v0 = xv[w][nl][i * 3 + 0];
                float v1 = xv[w][nl][i * 3 + 1];
                float v2 = xv[w][nl][i * 3 + 2];
                C[nl][0][0] += v0 * w0; C[nl][0][1] += v1 * w0; C[nl][0][2] += v2 * w0;
                C[nl][1][0] += v0 * w1; C[nl][1][1] += v1 * w1; C[nl][1][2] += v2 * w1;
            }
        }
#pragma unroll
        for (int nl = 0; nl < 2; nl++) {
            float* sc = g_sc + (size_t)(n0 + nl) * 320;
#pragma unroll
            for (int q = 0; q < 4; q++) sc[t + 32 * q] = S[nl][q] * INV64F;
#pragma unroll
            for (int c = 0; c < 3; c++) {
                sc[128 + t * 3 + c]        = C[nl][0][c] * INV64F;
                sc[128 + (t + 32) * 3 + c] = C[nl][1][c] * INV64F;
            }
        }
    }
}

// =====================================================================
// Kernel 2: edge kernel — radial MLP (FFMA2, edge-pair packed) +
// tensor-product message + scatter. Warp handles 8 edges, 4 warps/block.
// =====================================================================
#define EPW 8
#define K2W 4
__global__ void __launch_bounds__(128) k_edge(
    const float* __restrict__ vectors, const int* __restrict__ senders,
    const int* __restrict__ receivers, const float* __restrict__ W1,
    const float* __restrict__ W2, const float* __restrict__ W3)
{
    extern __shared__ __align__(16) float dyn[];
    float* rb_sm  = dyn;                    // [K2W][8][8]
    float* len_sm = rb_sm + K2W * 64;       // [K2W][8]
    float* h1_sm  = len_sm + K2W * 8;       // [K2W][64][8]  (edge innermost)
    float* h2_sm  = h1_sm + K2W * 512;      // [K2W][64][8]
    float* mix_sm = h2_sm + K2W * 512;      // [K2W][8][256]

    int w = threadIdx.x >> 5, t = threadIdx.x & 31;
    int e0 = (blockIdx.x * K2W + w) * EPW;

    // ---- phase 0: radial basis, distributed ----
#pragma unroll
    for (int r = 0; r < 2; r++) {
        int el = (t >> 3) + 4 * r;
        int k = t & 7;
        int e = e0 + el;
        float v0 = __ldg(vectors + e * 3 + 0);
        float v1 = __ldg(vectors + e * 3 + 1);
        float v2 = __ldg(vectors + e * 3 + 2);
        float len = sqrtf(v0 * v0 + v1 * v1 + v2 * v2);
        float x = len;
        float x2 = x * x, x3 = x2 * x, x6 = x3 * x3, x7 = x6 * x, x8 = x7 * x;
        float env = (x < 1.f) ? (1.f - 28.f * x6 + 48.f * x7 - 21.f * x8) : 0.f;
        float safe = (len == 0.f) ? 1.f : len;
        float rb = (len == 0.f) ? 0.f
                 : SQRT2F * sinf((float)(k + 1) * PI_F * len) / safe * env;
        rb_sm[(w * 8 + el) * 8 + k] = rb;
        if (k == 0) len_sm[w * 8 + el] = len;
    }
    __syncwarp();

    // ---- phase 1: h1 = swish(rb @ W1 * INV8), stored [i][e] ----
    {
        float w1a[8], w1b[8];
#pragma unroll
        for (int k = 0; k < 8; k++) {
            w1a[k] = __ldg(W1 + k * 64 + t);
            w1b[k] = __ldg(W1 + k * 64 + t + 32);
        }
#pragma unroll
        for (int e = 0; e < EPW; e++) {
            float a = 0.f, b = 0.f;
#pragma unroll
            for (int k = 0; k < 8; k++) {
                float r = rb_sm[(w * 8 + e) * 8 + k];
                a += r * w1a[k]; b += r * w1b[k];
            }
            h1_sm[(w * 64 + t) * 8 + e]      = swishf(a * INV8F);
            h1_sm[(w * 64 + t + 32) * 8 + e] = swishf(b * INV8F);
        }
    }
    __syncwarp();

    // ---- phase 2: h2 = swish(h1 @ W2 * INV64), FFMA2 over edge pairs ----
    {
        u64 acc0[4] = {0,0,0,0}, acc1[4] = {0,0,0,0};
#pragma unroll 4
        for (int i = 0; i < 64; i++) {
            float wa = __ldg(W2 + i * 64 + t);
            float wb = __ldg(W2 + i * 64 + t + 32);
            u64 wpa = pack2(wa, wa), wpb = pack2(wb, wb);
            const u64* hp = (const u64*)(h1_sm + (w * 64 + i) * 8);
#pragma unroll
            for (int p = 0; p < 4; p++) {
                u64 h = hp[p];
                ffma2(acc0[p], wpa, h);
                ffma2(acc1[p], wpb, h);
            }
        }
#pragma unroll
        for (int p = 0; p < 4; p++) {
            float2 v0 = unpack2(acc0[p]);
            float2 v1 = unpack2(acc1[p]);
            h2_sm[(w * 64 + t) * 8 + 2 * p]          = swishf(v0.x * INV64F);
            h2_sm[(w * 64 + t) * 8 + 2 * p + 1]      = swishf(v0.y * INV64F);
            h2_sm[(w * 64 + t + 32) * 8 + 2 * p]     = swishf(v1.x * INV64F);
            h2_sm[(w * 64 + t + 32) * 8 + 2 * p + 1] = swishf(v1.y * INV64F);
        }
    }
    __syncwarp();

    // ---- phase 3: mix = h2 @ W3 * INV64, FFMA2 over edge pairs ----
    {
        u64 acc[8][4];
#pragma unroll
        for (int j = 0; j < 8; j++)
#pragma unroll
            for (int p = 0; p < 4; p++) acc[j][p] = 0;
#pragma unroll 1
        for (int i = 0; i < 64; i++) {
            const u64* hp = (const u64*)(h2_sm + (w * 64 + i) * 8);
            u64 h0 = hp[0], h1 = hp[1], h2 = hp[2], h3 = hp[3];
#pragma unroll
            for (int j = 0; j < 8; j++) {
                float ww = __ldg(W3 + i * 256 + t + 32 * j);
                u64 wp = pack2(ww, ww);
                ffma2(acc[j][0], wp, h0);
                ffma2(acc[j][1], wp, h1);
                ffma2(acc[j][2], wp, h2);
                ffma2(acc[j][3], wp, h3);
            }
        }
#pragma unroll
        for (int j = 0; j < 8; j++)
#pragma unroll
            for (int p = 0; p < 4; p++) {
                float2 v = unpack2(acc[j][p]);
                mix_sm[(w * 8 + 2 * p) * 256 + t + 32 * j]     = v.x * INV64F;
                mix_sm[(w * 8 + 2 * p + 1) * 256 + t + 32 * j] = v.y * INV64F;
            }
    }
    __syncwarp();

    // ---- phase 4: gather, CG tensor product, scatter-add ----
#pragma unroll 1
    for (int el = 0; el < EPW; el++) {
        int e = e0 + el;
        int s = __ldg(senders + e);
        int r = __ldg(receivers + e);
        float len = len_sm[w * 8 + el];
        float inv = 1.f / ((len == 0.f) ? 1.f : len);
        float u0 = __ldg(vectors + e * 3 + 0) * inv;
        float u1 = __ldg(vectors + e * 3 + 1) * inv;
        float u2 = __ldg(vectors + e * 3 + 2) * inv;
        float y0 = SQRT3F * u0, y1 = SQRT3F * u1, y2 = SQRT3F * u2;

        int j = 4 * (t & 15);
        const float4 ms  = *(const float4*)(g_hs +              s * 64 + j);
        const float4 mv0 = *(const float4*)(g_hv + 0 * NPLANE + s * 64 + j);
        const float4 mv1 = *(const float4*)(g_hv + 1 * NPLANE + s * 64 + j);
        const float4 mv2 = *(const float4*)(g_hv + 2 * NPLANE + s * 64 + j);

        const float* mx = mix_sm + (w * 8 + el) * 256;
        float4 m1 = *(const float4*)(mx + 4 * t);
        float4 m2 = *(const float4*)(mx + 128 + 4 * t);

        float4 os, ov0, ov1, ov2;
        if (t < 16) {
            os  = make_float4(ms.x * m1.x, ms.y * m1.y, ms.z * m1.z, ms.w * m1.w);
            ov0 = make_float4(mv0.x * m2.x, mv0.y * m2.y, mv0.z * m2.z, mv0.w * m2.w);
            ov1 = make_float4(mv1.x * m2.x, mv1.y * m2.y, mv1.z * m2.z, mv1.w * m2.w);
            ov2 = make_float4(mv2.x * m2.x, mv2.y * m2.y, mv2.z * m2.z, mv2.w * m2.w);
        } else {
            float tpx = mv0.x * u0 + mv1.x * u1 + mv2.x * u2;
            float tpy = mv0.y * u0 + mv1.y * u1 + mv2.y * u2;
            float tpz = mv0.z * u0 + mv1.z * u1 + mv2.z * u2;
            float tpw = mv0.w * u0 + mv1.w * u1 + mv2.w * u2;
            os  = make_float4(tpx * m1.x, tpy * m1.y, tpz * m1.z, tpw * m1.w);
            ov0 = make_float4(ms.x * y0 * m2.x, ms.y * y0 * m2.y, ms.z * y0 * m2.z, ms.w * y0 * m2.w);
            ov1 = make_float4(ms.x * y1 * m2.x, ms.y * y1 * m2.y, ms.z * y1 * m2.z, ms.w * y1 * m2.w);
            ov2 = make_float4(ms.x * y2 * m2.x, ms.y * y2 * m2.y, ms.z * y2 * m2.z, ms.w * y2 * m2.w);
        }
        float* base = g_agg + (size_t)r * 512;
        atomicAdd((float4*)(base + 4 * t),       os);
        atomicAdd((float4*)(base + 128 + 4 * t), ov0);
        atomicAdd((float4*)(base + 256 + 4 * t), ov1);
        atomicAdd((float4*)(base + 384 + 4 * t), ov2);
    }
}

// =====================================================================
// Kernel 3: node "down" + skip + gate. Warp handles 4 nodes (FFMA2 pairs).
// 4 warps/block -> 16 nodes/block.
// =====================================================================
__global__ void __launch_bounds__(128) k_node_down(
    const float* __restrict__ Wds, const float* __restrict__ Wdv,
    float* __restrict__ out)
{
    __shared__ __align__(16) float agi[4][512][4];  // [warp][i][node]
    int w = threadIdx.x >> 5, t = threadIdx.x & 31;
    int n0 = (blockIdx.x * 4 + w) * 4;

    // stage 4 nodes, interleaved node-innermost
#pragma unroll
    for (int nl = 0; nl < 4; nl++) {
        const float4* src = (const float4*)(g_agg + (size_t)(n0 + nl) * 512);
#pragma unroll
        for (int q = 0; q < 4; q++) {
            float4 v = src[t + 32 * q];
            int i = 4 * t + 128 * q;
            agi[w][i + 0][nl] = v.x;
            agi[w][i + 1][nl] = v.y;
            agi[w][i + 2][nl] = v.z;
            agi[w][i + 3][nl] = v.w;
        }
    }
    __syncwarp();

    const float SCALE = INV128F * INVNN;

    // scalar part: ds[q] for q outputs t+32q, 4 nodes as 2 pairs
    u64 accS[4][2] = {};
#pragma unroll 2
    for (int i = 0; i < 128; i++) {
        const u64* xp = (const u64*)agi[w][i];
        u64 x0 = xp[0], x1 = xp[1];
#pragma unroll
        for (int q = 0; q < 4; q++) {
            float ww = __ldg(Wds + i * 128 + t + 32 * q);
            u64 wp = pack2(ww, ww);
            ffma2(accS[q][0], wp, x0);
            ffma2(accS[q][1], wp, x1);
        }
    }

    // vector part: outputs o = t, t+32; comps c; 2 node pairs
    u64 accV[2][3][2] = {};
#pragma unroll 2
    for (int i = 0; i < 128; i++) {
        float w0 = __ldg(Wdv + i * 64 + t);
        float w1 = __ldg(Wdv + i * 64 + t + 32);
        u64 wp0 = pack2(w0, w0), wp1 = pack2(w1, w1);
#pragma unroll
        for (int c = 0; c < 3; c++) {
            const u64* xp = (const u64*)agi[w][128 + 128 * c + i];
            u64 x0 = xp[0], x1 = xp[1];
            ffma2(accV[0][c][0], wp0, x0);
            ffma2(accV[0][c][1], wp0, x1);
            ffma2(accV[1][c][0], wp1, x0);
            ffma2(accV[1][c][1], wp1, x1);
        }
    }

#pragma unroll
    for (int nl = 0; nl < 4; nl++) {
        int n = n0 + nl;
        int p = nl >> 1, hi = nl & 1;
        const float* sc = g_sc + (size_t)n * 320;
        float ds[4];
#pragma unroll
        for (int q = 0; q < 4; q++) {
            float2 v = unpack2(accS[q][p]);
            ds[q] = (hi ? v.y : v.x) * SCALE + sc[t + 32 * q];
        }
        float g0 = swishf(ds[2]);
        float g1 = swishf(ds[3]);
        float* o = out + (size_t)n * 256;
        o[t]      = swishf(ds[0]);
        o[t + 32] = swishf(ds[1]);
#pragma unroll
        for (int c = 0; c < 3; c++) {
            float2 v0 = unpack2(accV[0][c][p]);
            float2 v1 = unpack2(accV[1][c][p]);
            float d0 = (hi ? v0.y : v0.x) * SCALE + sc[128 + t * 3 + c];
            float d1 = (hi ? v1.y : v1.x) * SCALE + sc[128 + (t + 32) * 3 + c];
            o[64 + t * 3 + c]        = d0 * g0;
            o[64 + (t + 32) * 3 + c] = d1 * g1;
        }
    }
}

// =====================================================================
extern "C" void kernel_launch(void* const* d_in, const int* in_sizes, int n_in,
                              void* d_out, int out_size)
{
    const float* vectors      = (const float*)d_in[0];
    const float* node_scalars = (const float*)d_in[1];
    const float* node_vectors = (const float*)d_in[2];
    const int*   node_specie  = (const int*)  d_in[3];
    const int*   senders      = (const int*)  d_in[4];
    const int*   receivers    = (const int*)  d_in[5];
    const float* W_up_s       = (const float*)d_in[6];
    const float* W_up_v       = (const float*)d_in[7];
    const float* W_skip_s     = (const float*)d_in[8];
    const float* W_skip_v     = (const float*)d_in[9];
    const float* W_mlp1       = (const float*)d_in[10];
    const float* W_mlp2       = (const float*)d_in[11];
    const float* W_mlp3       = (const float*)d_in[12];
    const float* W_down_s     = (const float*)d_in[13];
    const float* W_down_v     = (const float*)d_in[14];
    float* out = (float*)d_out;

    void* aggp = nullptr;
    cudaGetSymbolAddress(&aggp, g_agg);
    cudaMemsetAsync(aggp, 0, (size_t)N_NODES * 512 * sizeof(float));

    k_node_up<<<N_NODES / 16, 256>>>(node_scalars, node_vectors, node_specie,
                                     W_up_s, W_up_v, W_skip_s, W_skip_v);

    const int EDGE_SMEM = (K2W * 64 + K2W * 8 + K2W * 512 * 2 + K2W * 8 * 256) * 4;
    cudaFuncSetAttribute(k_edge, cudaFuncAttributeMaxDynamicSharedMemorySize, EDGE_SMEM);
    k_edge<<<N_EDGES / (K2W * EPW), 128, EDGE_SMEM>>>(vectors, senders, receivers,
                                                      W_mlp1, W_mlp2, W_mlp3);

    k_node_down<<<N_NODES / 16, 128>>>(W_down_s, W_down_v, out);
}

// round 3
// speedup vs baseline: 1.0200x; 1.0200x over previous
#include <cuda_runtime.h>
#include <cuda_bf16.h>

#define N_NODES 40000
#define N_EDGES 480000
#define NPLANE  (N_NODES * 64)

__device__ __align__(16) float g_hs[N_NODES * 64];
__device__ __align__(16) float g_hv[3 * N_NODES * 64];
__device__ __align__(16) float g_sc[N_NODES * 320];
__device__ __align__(16) float g_agg[(size_t)N_NODES * 512];
__device__ int g_cnt[N_NODES];      // histogram, then cursor
__device__ int g_perm[N_EDGES];

__device__ __forceinline__ float swishf(float x) {
    return x / (1.0f + __expf(-x));
}

typedef unsigned long long u64;

__device__ __forceinline__ u64 pack2(float lo, float hi) {
    u64 r; asm("mov.b64 %0, {%1, %2};" : "=l"(r) : "f"(lo), "f"(hi)); return r;
}
__device__ __forceinline__ float2 unpack2(u64 v) {
    float2 r; asm("mov.b64 {%0, %1}, %2;" : "=f"(r.x), "=f"(r.y) : "l"(v)); return r;
}
__device__ __forceinline__ void ffma2(u64& d, u64 a, u64 b) {
    asm("fma.rn.f32x2 %0, %1, %2, %0;" : "+l"(d) : "l"(a), "l"(b));
}

#define INV8F   0.3535533905932738f
#define INV64F  0.125f
#define INV128F 0.08838834764831845f
#define INVNN   0.28867513459481287f
#define SQRT3F  1.7320508075688772f
#define SQRT2F  1.4142135623730951f
#define PI_F    3.14159265358979323846f

// =====================================================================
// Sort infrastructure: histogram -> single-block scan -> scatter
// =====================================================================
__global__ void k_hist(const int* __restrict__ receivers) {
    int e = blockIdx.x * blockDim.x + threadIdx.x;
    if (e < N_EDGES) atomicAdd(&g_cnt[__ldg(receivers + e)], 1);
}

#define SCAN_T 1024
#define SCAN_C 40   // ceil(40000/1024) = 40
__global__ void __launch_bounds__(SCAN_T) k_scan() {
    __shared__ int psum[SCAN_T];
    int tid = threadIdx.x;
    int base = tid * SCAN_C;
    int local[SCAN_C];
    int s = 0;
#pragma unroll
    for (int i = 0; i < SCAN_C; i++) {
        int idx = base + i;
        int v = (idx < N_NODES) ? g_cnt[idx] : 0;
        local[i] = v; s += v;
    }
    psum[tid] = s;
    __syncthreads();
    // Hillis-Steele inclusive scan
    for (int d = 1; d < SCAN_T; d <<= 1) {
        int v = (tid >= d) ? psum[tid - d] : 0;
        __syncthreads();
        psum[tid] += v;
        __syncthreads();
    }
    int off = psum[tid] - s;   // exclusive prefix
#pragma unroll
    for (int i = 0; i < SCAN_C; i++) {
        int idx = base + i;
        if (idx < N_NODES) { g_cnt[idx] = off; off += local[i]; }
    }
}

__global__ void k_scatter(const int* __restrict__ receivers) {
    int e = blockIdx.x * blockDim.x + threadIdx.x;
    if (e < N_EDGES) {
        int pos = atomicAdd(&g_cnt[__ldg(receivers + e)], 1);
        g_perm[pos] = e;
    }
}

// =====================================================================
// Kernel 1: per-node "up" linear + species skip (R1 version: warp/node)
// =====================================================================
__global__ void k_node_up(const float* __restrict__ ns, const float* __restrict__ nv,
                          const int* __restrict__ specie,
                          const float* __restrict__ Wus, const float* __restrict__ Wuv,
                          const float* __restrict__ Wss, const float* __restrict__ Wsv)
{
    __shared__ __align__(16) float xs[8][64];
    __shared__ __align__(16) float xv[8][192];
    int w = threadIdx.x >> 5, t = threadIdx.x & 31;
    int n = blockIdx.x * 8 + w;
    if (n >= N_NODES) return;

    xs[w][t]      = __ldg(ns + n * 64 + t);
    xs[w][t + 32] = __ldg(ns + n * 64 + t + 32);
#pragma unroll
    for (int q = 0; q < 6; q++)
        xv[w][t + 32 * q] = __ldg(nv + n * 192 + t + 32 * q);
    __syncwarp();

    int sp = __ldg(specie + n);
    const float* Ws = Wss + sp * 64 * 128;
    const float* Wv = Wsv + sp * 64 * 64;

    float a0 = 0.f, a1 = 0.f;
    float b[2][3] = {{0.f,0.f,0.f},{0.f,0.f,0.f}};
#pragma unroll 4
    for (int i = 0; i < 64; i++) {
        float x = xs[w][i];
        a0 += x * __ldg(Wus + i * 64 + t);
        a1 += x * __ldg(Wus + i * 64 + t + 32);
        float wv0 = __ldg(Wuv + i * 64 + t);
        float wv1 = __ldg(Wuv + i * 64 + t + 32);
        float xv0 = xv[w][i * 3 + 0], xv1 = xv[w][i * 3 + 1], xv2 = xv[w][i * 3 + 2];
        b[0][0] += xv0 * wv0; b[0][1] += xv1 * wv0; b[0][2] += xv2 * wv0;
        b[1][0] += xv0 * wv1; b[1][1] += xv1 * wv1; b[1][2] += xv2 * wv1;
    }
    g_hs[n * 64 + t]      = a0 * INV64F;
    g_hs[n * 64 + t + 32] = a1 * INV64F;
#pragma unroll
    for (int c = 0; c < 3; c++) {
        g_hv[c * NPLANE + n * 64 + t]      = b[0][c] * INV64F;
        g_hv[c * NPLANE + n * 64 + t + 32] = b[1][c] * INV64F;
    }

    float s4[4] = {0.f,0.f,0.f,0.f};
    float c6[2][3] = {{0.f,0.f,0.f},{0.f,0.f,0.f}};
#pragma unroll 4
    for (int i = 0; i < 64; i++) {
        float x = xs[w][i];
#pragma unroll
        for (int q = 0; q < 4; q++)
            s4[q] += x * __ldg(Ws + i * 128 + t + 32 * q);
        float w0 = __ldg(Wv + i * 64 + t);
        float w1 = __ldg(Wv + i * 64 + t + 32);
        float xv0 = xv[w][i * 3 + 0], xv1 = xv[w][i * 3 + 1], xv2 = xv[w][i * 3 + 2];
        c6[0][0] += xv0 * w0; c6[0][1] += xv1 * w0; c6[0][2] += xv2 * w0;
        c6[1][0] += xv0 * w1; c6[1][1] += xv1 * w1; c6[1][2] += xv2 * w1;
    }
    float* sc = g_sc + (size_t)n * 320;
#pragma unroll
    for (int q = 0; q < 4; q++) sc[t + 32 * q] = s4[q] * INV64F;
#pragma unroll
    for (int c = 0; c < 3; c++) {
        sc[128 + t * 3 + c]        = c6[0][c] * INV64F;
        sc[128 + (t + 32) * 3 + c] = c6[1][c] * INV64F;
    }
}

// =====================================================================
// Kernel 2: edge kernel over receiver-sorted permutation; run-merged
// atomic flushes. Warp handles 8 permuted edges, 4 warps/block.
// =====================================================================
#define EPW 8
#define K2W 4
__global__ void __launch_bounds__(128) k_edge(
    const float* __restrict__ vectors, const int* __restrict__ senders,
    const int* __restrict__ receivers, const float* __restrict__ W1,
    const float* __restrict__ W2, const float* __restrict__ W3)
{
    extern __shared__ __align__(16) float dyn[];
    float* rb_sm  = dyn;                    // [K2W][8][8]
    float* len_sm = rb_sm + K2W * 64;       // [K2W][8]
    float* h1_sm  = len_sm + K2W * 8;       // [K2W][64][8]  (edge innermost)
    float* h2_sm  = h1_sm + K2W * 512;      // [K2W][64][8]
    float* mix_sm = h2_sm + K2W * 512;      // [K2W][8][256]
    int*   eid_sm = (int*)(mix_sm + K2W * 8 * 256);  // [K2W][8]

    int w = threadIdx.x >> 5, t = threadIdx.x & 31;
    int e0 = (blockIdx.x * K2W + w) * EPW;

    if (t < EPW) eid_sm[w * EPW + t] = __ldg(g_perm + e0 + t);
    __syncwarp();

    // ---- phase 0: radial basis, distributed ----
#pragma unroll
    for (int r = 0; r < 2; r++) {
        int el = (t >> 3) + 4 * r;
        int k = t & 7;
        int e = eid_sm[w * EPW + el];
        float v0 = __ldg(vectors + e * 3 + 0);
        float v1 = __ldg(vectors + e * 3 + 1);
        float v2 = __ldg(vectors + e * 3 + 2);
        float len = sqrtf(v0 * v0 + v1 * v1 + v2 * v2);
        float x = len;
        float x2 = x * x, x3 = x2 * x, x6 = x3 * x3, x7 = x6 * x, x8 = x7 * x;
        float env = (x < 1.f) ? (1.f - 28.f * x6 + 48.f * x7 - 21.f * x8) : 0.f;
        float safe = (len == 0.f) ? 1.f : len;
        float rb = (len == 0.f) ? 0.f
                 : SQRT2F * sinf((float)(k + 1) * PI_F * len) / safe * env;
        rb_sm[(w * 8 + el) * 8 + k] = rb;
        if (k == 0) len_sm[w * 8 + el] = len;
    }
    __syncwarp();

    // ---- phase 1: h1 = swish(rb @ W1 * INV8), stored [i][e] ----
    {
        float w1a[8], w1b[8];
#pragma unroll
        for (int k = 0; k < 8; k++) {
            w1a[k] = __ldg(W1 + k * 64 + t);
            w1b[k] = __ldg(W1 + k * 64 + t + 32);
        }
#pragma unroll
        for (int e = 0; e < EPW; e++) {
            float a = 0.f, b = 0.f;
#pragma unroll
            for (int k = 0; k < 8; k++) {
                float r = rb_sm[(w * 8 + e) * 8 + k];
                a += r * w1a[k]; b += r * w1b[k];
            }
            h1_sm[(w * 64 + t) * 8 + e]      = swishf(a * INV8F);
            h1_sm[(w * 64 + t + 32) * 8 + e] = swishf(b * INV8F);
        }
    }
    __syncwarp();

    // ---- phase 2: h2 = swish(h1 @ W2 * INV64), FFMA2 edge pairs ----
    {
        u64 acc0[4] = {0,0,0,0}, acc1[4] = {0,0,0,0};
#pragma unroll 4
        for (int i = 0; i < 64; i++) {
            float wa = __ldg(W2 + i * 64 + t);
            float wb = __ldg(W2 + i * 64 + t + 32);
            u64 wpa = pack2(wa, wa), wpb = pack2(wb, wb);
            const u64* hp = (const u64*)(h1_sm + (w * 64 + i) * 8);
#pragma unroll
            for (int p = 0; p < 4; p++) {
                u64 h = hp[p];
                ffma2(acc0[p], wpa, h);
                ffma2(acc1[p], wpb, h);
            }
        }
#pragma unroll
        for (int p = 0; p < 4; p++) {
            float2 v0 = unpack2(acc0[p]);
            float2 v1 = unpack2(acc1[p]);
            h2_sm[(w * 64 + t) * 8 + 2 * p]          = swishf(v0.x * INV64F);
            h2_sm[(w * 64 + t) * 8 + 2 * p + 1]      = swishf(v0.y * INV64F);
            h2_sm[(w * 64 + t + 32) * 8 + 2 * p]     = swishf(v1.x * INV64F);
            h2_sm[(w * 64 + t + 32) * 8 + 2 * p + 1] = swishf(v1.y * INV64F);
        }
    }
    __syncwarp();

    // ---- phase 3: mix = h2 @ W3 * INV64, FFMA2 edge pairs ----
    {
        u64 acc[8][4];
#pragma unroll
        for (int j = 0; j < 8; j++)
#pragma unroll
            for (int p = 0; p < 4; p++) acc[j][p] = 0;
#pragma unroll 1
        for (int i = 0; i < 64; i++) {
            const u64* hp = (const u64*)(h2_sm + (w * 64 + i) * 8);
            u64 h0 = hp[0], h1 = hp[1], h2 = hp[2], h3 = hp[3];
#pragma unroll
            for (int j = 0; j < 8; j++) {
                float ww = __ldg(W3 + i * 256 + t + 32 * j);
                u64 wp = pack2(ww, ww);
                ffma2(acc[j][0], wp, h0);
                ffma2(acc[j][1], wp, h1);
                ffma2(acc[j][2], wp, h2);
                ffma2(acc[j][3], wp, h3);
            }
        }
#pragma unroll
        for (int j = 0; j < 8; j++)
#pragma unroll
            for (int p = 0; p < 4; p++) {
                float2 v = unpack2(acc[j][p]);
                mix_sm[(w * 8 + 2 * p) * 256 + t + 32 * j]     = v.x * INV64F;
                mix_sm[(w * 8 + 2 * p + 1) * 256 + t + 32 * j] = v.y * INV64F;
            }
    }
    __syncwarp();

    // ---- phase 4: gather, CG product, run-merged scatter ----
    {
        float4 aS  = make_float4(0,0,0,0), aV0 = make_float4(0,0,0,0);
        float4 aV1 = make_float4(0,0,0,0), aV2 = make_float4(0,0,0,0);
        int curr = -1;
        int j = 4 * (t & 15);
#pragma unroll 1
        for (int el = 0; el < EPW; el++) {
            int e = eid_sm[w * EPW + el];
            int s = __ldg(senders + e);
            int r = __ldg(receivers + e);
            float len = len_sm[w * 8 + el];
            float inv = 1.f / ((len == 0.f) ? 1.f : len);
            float u0 = __ldg(vectors + e * 3 + 0) * inv;
            float u1 = __ldg(vectors + e * 3 + 1) * inv;
            float u2 = __ldg(vectors + e * 3 + 2) * inv;
            float y0 = SQRT3F * u0, y1 = SQRT3F * u1, y2 = SQRT3F * u2;

            const float4 ms  = *(const float4*)(g_hs +              s * 64 + j);
            const float4 mv0 = *(const float4*)(g_hv + 0 * NPLANE + s * 64 + j);
            const float4 mv1 = *(const float4*)(g_hv + 1 * NPLANE + s * 64 + j);
            const float4 mv2 = *(const float4*)(g_hv + 2 * NPLANE + s * 64 + j);

            const float* mx = mix_sm + (w * 8 + el) * 256;
            float4 m1 = *(const float4*)(mx + 4 * t);
            float4 m2 = *(const float4*)(mx + 128 + 4 * t);

            float4 os, ov0, ov1, ov2;
            if (t < 16) {
                os  = make_float4(ms.x * m1.x, ms.y * m1.y, ms.z * m1.z, ms.w * m1.w);
                ov0 = make_float4(mv0.x * m2.x, mv0.y * m2.y, mv0.z * m2.z, mv0.w * m2.w);
                ov1 = make_float4(mv1.x * m2.x, mv1.y * m2.y, mv1.z * m2.z, mv1.w * m2.w);
                ov2 = make_float4(mv2.x * m2.x, mv2.y * m2.y, mv2.z * m2.z, mv2.w * m2.w);
            } else {
                float tpx = mv0.x * u0 + mv1.x * u1 + mv2.x * u2;
                float tpy = mv0.y * u0 + mv1.y * u1 + mv2.y * u2;
                float tpz = mv0.z * u0 + mv1.z * u1 + mv2.z * u2;
                float tpw = mv0.w * u0 + mv1.w * u1 + mv2.w * u2;
                os  = make_float4(tpx * m1.x, tpy * m1.y, tpz * m1.z, tpw * m1.w);
                ov0 = make_float4(ms.x * y0 * m2.x, ms.y * y0 * m2.y, ms.z * y0 * m2.z, ms.w * y0 * m2.w);
                ov1 = make_float4(ms.x * y1 * m2.x, ms.y * y1 * m2.y, ms.z * y1 * m2.z, ms.w * y1 * m2.w);
                ov2 = make_float4(ms.x * y2 * m2.x, ms.y * y2 * m2.y, ms.z * y2 * m2.z, ms.w * y2 * m2.w);
            }

            if (r != curr) {            // warp-uniform branch
                if (curr >= 0) {
                    float* base = g_agg + (size_t)curr * 512;
                    atomicAdd((float4*)(base + 4 * t),       aS);
                    atomicAdd((float4*)(base + 128 + 4 * t), aV0);
                    atomicAdd((float4*)(base + 256 + 4 * t), aV1);
                    atomicAdd((float4*)(base + 384 + 4 * t), aV2);
                }
                curr = r;
                aS = os; aV0 = ov0; aV1 = ov1; aV2 = ov2;
            } else {
                aS.x += os.x;  aS.y += os.y;  aS.z += os.z;  aS.w += os.w;
                aV0.x += ov0.x; aV0.y += ov0.y; aV0.z += ov0.z; aV0.w += ov0.w;
                aV1.x += ov1.x; aV1.y += ov1.y; aV1.z += ov1.z; aV1.w += ov1.w;
                aV2.x += ov2.x; aV2.y += ov2.y; aV2.z += ov2.z; aV2.w += ov2.w;
            }
        }
        if (curr >= 0) {
            float* base = g_agg + (size_t)curr * 512;
            atomicAdd((float4*)(base + 4 * t),       aS);
            atomicAdd((float4*)(base + 128 + 4 * t), aV0);
            atomicAdd((float4*)(base + 256 + 4 * t), aV1);
            atomicAdd((float4*)(base + 384 + 4 * t), aV2);
        }
    }
}

// =====================================================================
// Kernel 3: node "down" + skip + gate. Warp handles 4 nodes (FFMA2).
// =====================================================================
__global__ void __launch_bounds__(128) k_node_down(
    const float* __restrict__ Wds, const float* __restrict__ Wdv,
    float* __restrict__ out)
{
    __shared__ __align__(16) float agi[4][512][4];
    int w = threadIdx.x >> 5, t = threadIdx.x & 31;
    int n0 = (blockIdx.x * 4 + w) * 4;

#pragma unroll
    for (int nl = 0; nl < 4; nl++) {
        const float4* src = (const float4*)(g_agg + (size_t)(n0 + nl) * 512);
#pragma unroll
        for (int q = 0; q < 4; q++) {
            float4 v = src[t + 32 * q];
            int i = 4 * t + 128 * q;
            agi[w][i + 0][nl] = v.x;
            agi[w][i + 1][nl] = v.y;
            agi[w][i + 2][nl] = v.z;
            agi[w][i + 3][nl] = v.w;
        }
    }
    __syncwarp();

    const float SCALE = INV128F * INVNN;

    u64 accS[4][2] = {};
#pragma unroll 2
    for (int i = 0; i < 128; i++) {
        const u64* xp = (const u64*)agi[w][i];
        u64 x0 = xp[0], x1 = xp[1];
#pragma unroll
        for (int q = 0; q < 4; q++) {
            float ww = __ldg(Wds + i * 128 + t + 32 * q);
            u64 wp = pack2(ww, ww);
            ffma2(accS[q][0], wp, x0);
            ffma2(accS[q][1], wp, x1);
        }
    }

    u64 accV[2][3][2] = {};
#pragma unroll 2
    for (int i = 0; i < 128; i++) {
        float w0 = __ldg(Wdv + i * 64 + t);
        float w1 = __ldg(Wdv + i * 64 + t + 32);
        u64 wp0 = pack2(w0, w0), wp1 = pack2(w1, w1);
#pragma unroll
        for (int c = 0; c < 3; c++) {
            const u64* xp = (const u64*)agi[w][128 + 128 * c + i];
            u64 x0 = xp[0], x1 = xp[1];
            ffma2(accV[0][c][0], wp0, x0);
            ffma2(accV[0][c][1], wp0, x1);
            ffma2(accV[1][c][0], wp1, x0);
            ffma2(accV[1][c][1], wp1, x1);
        }
    }

#pragma unroll
    for (int nl = 0; nl < 4; nl++) {
        int n = n0 + nl;
        int p = nl >> 1, hi = nl & 1;
        const float* sc = g_sc + (size_t)n * 320;
        float ds[4];
#pragma unroll
        for (int q = 0; q < 4; q++) {
            float2 v = unpack2(accS[q][p]);
            ds[q] = (hi ? v.y : v.x) * SCALE + sc[t + 32 * q];
        }
        float g0 = swishf(ds[2]);
        float g1 = swishf(ds[3]);
        float* o = out + (size_t)n * 256;
        o[t]      = swishf(ds[0]);
        o[t + 32] = swishf(ds[1]);
#pragma unroll
        for (int c = 0; c < 3; c++) {
            float2 v0 = unpack2(accV[0][c][p]);
            float2 v1 = unpack2(accV[1][c][p]);
            float d0 = (hi ? v0.y : v0.x) * SCALE + sc[128 + t * 3 + c];
            float d1 = (hi ? v1.y : v1.x) * SCALE + sc[128 + (t + 32) * 3 + c];
            o[64 + t * 3 + c]        = d0 * g0;
            o[64 + (t + 32) * 3 + c] = d1 * g1;
        }
    }
}

// =====================================================================
extern "C" void kernel_launch(void* const* d_in, const int* in_sizes, int n_in,
                              void* d_out, int out_size)
{
    const float* vectors      = (const float*)d_in[0];
    const float* node_scalars = (const float*)d_in[1];
    const float* node_vectors = (const float*)d_in[2];
    const int*   node_specie  = (const int*)  d_in[3];
    const int*   senders      = (const int*)  d_in[4];
    const int*   receivers    = (const int*)  d_in[5];
    const float* W_up_s       = (const float*)d_in[6];
    const float* W_up_v       = (const float*)d_in[7];
    const float* W_skip_s     = (const float*)d_in[8];
    const float* W_skip_v     = (const float*)d_in[9];
    const float* W_mlp1       = (const float*)d_in[10];
    const float* W_mlp2       = (const float*)d_in[11];
    const float* W_mlp3       = (const float*)d_in[12];
    const float* W_down_s     = (const float*)d_in[13];
    const float* W_down_v     = (const float*)d_in[14];
    float* out = (float*)d_out;

    void* aggp = nullptr; cudaGetSymbolAddress(&aggp, g_agg);
    void* cntp = nullptr; cudaGetSymbolAddress(&cntp, g_cnt);
    cudaMemsetAsync(aggp, 0, (size_t)N_NODES * 512 * sizeof(float));
    cudaMemsetAsync(cntp, 0, N_NODES * sizeof(int));

    // build receiver-sorted permutation
    k_hist<<<(N_EDGES + 255) / 256, 256>>>(receivers);
    k_scan<<<1, SCAN_T>>>();
    k_scatter<<<(N_EDGES + 255) / 256, 256>>>(receivers);

    k_node_up<<<(N_NODES + 7) / 8, 256>>>(node_scalars, node_vectors, node_specie,
                                          W_up_s, W_up_v, W_skip_s, W_skip_v);

    const int EDGE_SMEM = (K2W * 64 + K2W * 8 + K2W * 512 * 2 + K2W * 8 * 256 + K2W * 8) * 4;
    cudaFuncSetAttribute(k_edge, cudaFuncAttributeMaxDynamicSharedMemorySize, EDGE_SMEM);
    k_edge<<<N_EDGES / (K2W * EPW), 128, EDGE_SMEM>>>(vectors, senders, receivers,
                                                      W_mlp1, W_mlp2, W_mlp3);

    k_node_down<<<N_NODES / 16, 128>>>(W_down_s, W_down_v, out);
}

// round 4
// speedup vs baseline: 2.0540x; 2.0138x over previous
#include <cuda_runtime.h>
#include <cuda_bf16.h>

#define N_NODES 40000
#define N_EDGES 480000
#define NPLANE  (N_NODES * 64)

#define TBL    4096
#define LMAXF  0.86603f
#define HSTEP  (LMAXF / (TBL - 1))
#define INVH   ((TBL - 1) / LMAXF)

__device__ __align__(16) float g_hs[N_NODES * 64];
__device__ __align__(16) float g_hv[3 * N_NODES * 64];
__device__ __align__(16) float g_sc[N_NODES * 320];
__device__ __align__(16) float g_agg[(size_t)N_NODES * 512];
__device__ __align__(16) float g_tbl[TBL * 256];
__device__ int g_cnt[N_NODES];
__device__ int g_perm[N_EDGES];

__device__ __forceinline__ float swishf(float x) {
    return x / (1.0f + __expf(-x));
}

typedef unsigned long long u64;
__device__ __forceinline__ u64 pack2(float lo, float hi) {
    u64 r; asm("mov.b64 %0, {%1, %2};" : "=l"(r) : "f"(lo), "f"(hi)); return r;
}
__device__ __forceinline__ float2 unpack2(u64 v) {
    float2 r; asm("mov.b64 {%0, %1}, %2;" : "=f"(r.x), "=f"(r.y) : "l"(v)); return r;
}
__device__ __forceinline__ void ffma2(u64& d, u64 a, u64 b) {
    asm("fma.rn.f32x2 %0, %1, %2, %0;" : "+l"(d) : "l"(a), "l"(b));
}

#define INV8F   0.3535533905932738f
#define INV64F  0.125f
#define INV128F 0.08838834764831845f
#define INVNN   0.28867513459481287f
#define SQRT3F  1.7320508075688772f
#define SQRT2F  1.4142135623730951f
#define PI_F    3.14159265358979323846f

// =====================================================================
// Sort infrastructure
// =====================================================================
__global__ void k_hist(const int* __restrict__ receivers) {
    int e = blockIdx.x * blockDim.x + threadIdx.x;
    if (e < N_EDGES) atomicAdd(&g_cnt[__ldg(receivers + e)], 1);
}

#define SCAN_T 1024
#define SCAN_C 40
__global__ void __launch_bounds__(SCAN_T) k_scan() {
    __shared__ int psum[SCAN_T];
    int tid = threadIdx.x;
    int base = tid * SCAN_C;
    int local[SCAN_C];
    int s = 0;
#pragma unroll
    for (int i = 0; i < SCAN_C; i++) {
        int idx = base + i;
        int v = (idx < N_NODES) ? g_cnt[idx] : 0;
        local[i] = v; s += v;
    }
    psum[tid] = s;
    __syncthreads();
    for (int d = 1; d < SCAN_T; d <<= 1) {
        int v = (tid >= d) ? psum[tid - d] : 0;
        __syncthreads();
        psum[tid] += v;
        __syncthreads();
    }
    int off = psum[tid] - s;
#pragma unroll
    for (int i = 0; i < SCAN_C; i++) {
        int idx = base + i;
        if (idx < N_NODES) { g_cnt[idx] = off; off += local[i]; }
    }
}

__global__ void k_scatter(const int* __restrict__ receivers) {
    int e = blockIdx.x * blockDim.x + threadIdx.x;
    if (e < N_EDGES) {
        int pos = atomicAdd(&g_cnt[__ldg(receivers + e)], 1);
        g_perm[pos] = e;
    }
}

// =====================================================================
// Table builder: mix(len) for TBL grid points. 256 threads/block,
// 16 rows per block (4 groups of 64 threads), W2/W3 staged in smem.
// =====================================================================
__global__ void __launch_bounds__(256) k_table(
    const float* __restrict__ W1, const float* __restrict__ W2,
    const float* __restrict__ W3)
{
    extern __shared__ float smw[];
    float* sW2 = smw;            // 64*64
    float* sW3 = smw + 4096;     // 64*256
    __shared__ float rb_s[4][8], h1_s[4][64], h2_s[4][64];
    int tid = threadIdx.x;
    for (int i = tid; i < 4096; i += 256)  sW2[i] = __ldg(W2 + i);
    for (int i = tid; i < 16384; i += 256) sW3[i] = __ldg(W3 + i);
    __syncthreads();

    int g = tid >> 6, t = tid & 63;
#pragma unroll 1
    for (int rep = 0; rep < 4; rep++) {
        int row = blockIdx.x * 16 + rep * 4 + g;
        float x = row * HSTEP;
        if (t < 8) {
            float k = (float)(t + 1);
            float s = (x > 0.f) ? (sinf(k * PI_F * x) / x) : (k * PI_F);
            float x2 = x * x, x3 = x2 * x, x6 = x3 * x3, x7 = x6 * x, x8 = x7 * x;
            float env = (x < 1.f) ? (1.f - 28.f * x6 + 48.f * x7 - 21.f * x8) : 0.f;
            rb_s[g][t] = SQRT2F * s * env;
        }
        __syncthreads();
        float a = 0.f;
#pragma unroll
        for (int k = 0; k < 8; k++) a += rb_s[g][k] * __ldg(W1 + k * 64 + t);
        h1_s[g][t] = swishf(a * INV8F);
        __syncthreads();
        float b = 0.f;
#pragma unroll 8
        for (int i = 0; i < 64; i++) b += h1_s[g][i] * sW2[i * 64 + t];
        h2_s[g][t] = swishf(b * INV64F);
        __syncthreads();
#pragma unroll
        for (int jj = 0; jj < 4; jj++) {
            float c = 0.f;
#pragma unroll 8
            for (int i = 0; i < 64; i++) c += h2_s[g][i] * sW3[i * 256 + t + 64 * jj];
            g_tbl[row * 256 + t + 64 * jj] = c * INV64F;
        }
        __syncthreads();
    }
}

// =====================================================================
// Kernel 1: per-node "up" linear + species skip (warp/node)
// =====================================================================
__global__ void k_node_up(const float* __restrict__ ns, const float* __restrict__ nv,
                          const int* __restrict__ specie,
                          const float* __restrict__ Wus, const float* __restrict__ Wuv,
                          const float* __restrict__ Wss, const float* __restrict__ Wsv)
{
    __shared__ __align__(16) float xs[8][64];
    __shared__ __align__(16) float xv[8][192];
    int w = threadIdx.x >> 5, t = threadIdx.x & 31;
    int n = blockIdx.x * 8 + w;
    if (n >= N_NODES) return;

    xs[w][t]      = __ldg(ns + n * 64 + t);
    xs[w][t + 32] = __ldg(ns + n * 64 + t + 32);
#pragma unroll
    for (int q = 0; q < 6; q++)
        xv[w][t + 32 * q] = __ldg(nv + n * 192 + t + 32 * q);
    __syncwarp();

    int sp = __ldg(specie + n);
    const float* Ws = Wss + sp * 64 * 128;
    const float* Wv = Wsv + sp * 64 * 64;

    float a0 = 0.f, a1 = 0.f;
    float b[2][3] = {{0.f,0.f,0.f},{0.f,0.f,0.f}};
#pragma unroll 4
    for (int i = 0; i < 64; i++) {
        float x = xs[w][i];
        a0 += x * __ldg(Wus + i * 64 + t);
        a1 += x * __ldg(Wus + i * 64 + t + 32);
        float wv0 = __ldg(Wuv + i * 64 + t);
        float wv1 = __ldg(Wuv + i * 64 + t + 32);
        float xv0 = xv[w][i * 3 + 0], xv1 = xv[w][i * 3 + 1], xv2 = xv[w][i * 3 + 2];
        b[0][0] += xv0 * wv0; b[0][1] += xv1 * wv0; b[0][2] += xv2 * wv0;
        b[1][0] += xv0 * wv1; b[1][1] += xv1 * wv1; b[1][2] += xv2 * wv1;
    }
    g_hs[n * 64 + t]      = a0 * INV64F;
    g_hs[n * 64 + t + 32] = a1 * INV64F;
#pragma unroll
    for (int c = 0; c < 3; c++) {
        g_hv[c * NPLANE + n * 64 + t]      = b[0][c] * INV64F;
        g_hv[c * NPLANE + n * 64 + t + 32] = b[1][c] * INV64F;
    }

    float s4[4] = {0.f,0.f,0.f,0.f};
    float c6[2][3] = {{0.f,0.f,0.f},{0.f,0.f,0.f}};
#pragma unroll 4
    for (int i = 0; i < 64; i++) {
        float x = xs[w][i];
#pragma unroll
        for (int q = 0; q < 4; q++)
            s4[q] += x * __ldg(Ws + i * 128 + t + 32 * q);
        float w0 = __ldg(Wv + i * 64 + t);
        float w1 = __ldg(Wv + i * 64 + t + 32);
        float xv0 = xv[w][i * 3 + 0], xv1 = xv[w][i * 3 + 1], xv2 = xv[w][i * 3 + 2];
        c6[0][0] += xv0 * w0; c6[0][1] += xv1 * w0; c6[0][2] += xv2 * w0;
        c6[1][0] += xv0 * w1; c6[1][1] += xv1 * w1; c6[1][2] += xv2 * w1;
    }
    float* sc = g_sc + (size_t)n * 320;
#pragma unroll
    for (int q = 0; q < 4; q++) sc[t + 32 * q] = s4[q] * INV64F;
#pragma unroll
    for (int c = 0; c < 3; c++) {
        sc[128 + t * 3 + c]        = c6[0][c] * INV64F;
        sc[128 + (t + 32) * 3 + c] = c6[1][c] * INV64F;
    }
}

// =====================================================================
// Kernel 2: edge kernel — table-interp mix + gather + CG + merged scatter
// warp handles EPW sorted edges; no heavy smem -> high occupancy
// =====================================================================
#define EPW 8
#define K2W 8
__global__ void __launch_bounds__(256) k_edge(
    const float* __restrict__ vectors, const int* __restrict__ senders,
    const int* __restrict__ receivers)
{
    int w = threadIdx.x >> 5, t = threadIdx.x & 31;
    int e0 = (blockIdx.x * K2W + w) * EPW;

    float4 aS  = make_float4(0,0,0,0), aV0 = make_float4(0,0,0,0);
    float4 aV1 = make_float4(0,0,0,0), aV2 = make_float4(0,0,0,0);
    int curr = -1;
    int j = 4 * (t & 15);

#pragma unroll 1
    for (int el = 0; el < EPW; el++) {
        int e = __ldg(g_perm + e0 + el);
        int s = __ldg(senders + e);
        int r = __ldg(receivers + e);

        float v0 = __ldg(vectors + e * 3 + 0);
        float v1 = __ldg(vectors + e * 3 + 1);
        float v2 = __ldg(vectors + e * 3 + 2);
        float len = sqrtf(v0 * v0 + v1 * v1 + v2 * v2);
        float inv = 1.f / ((len == 0.f) ? 1.f : len);
        float u0 = v0 * inv, u1 = v1 * inv, u2 = v2 * inv;
        float y0 = SQRT3F * u0, y1 = SQRT3F * u1, y2 = SQRT3F * u2;

        // mix via table lerp
        float uu = len * INVH;
        int i0 = (int)uu;
        if (i0 > TBL - 2) i0 = TBL - 2;
        float f = uu - (float)i0;
        const float* r0 = g_tbl + i0 * 256;
        const float* r1 = r0 + 256;
        float4 p0 = *(const float4*)(r0 + 4 * t);
        float4 p1 = *(const float4*)(r1 + 4 * t);
        float4 q0 = *(const float4*)(r0 + 128 + 4 * t);
        float4 q1 = *(const float4*)(r1 + 128 + 4 * t);
        float4 m1 = make_float4(p0.x + f * (p1.x - p0.x), p0.y + f * (p1.y - p0.y),
                                p0.z + f * (p1.z - p0.z), p0.w + f * (p1.w - p0.w));
        float4 m2 = make_float4(q0.x + f * (q1.x - q0.x), q0.y + f * (q1.y - q0.y),
                                q0.z + f * (q1.z - q0.z), q0.w + f * (q1.w - q0.w));

        const float4 ms  = *(const float4*)(g_hs +              s * 64 + j);
        const float4 mv0 = *(const float4*)(g_hv + 0 * NPLANE + s * 64 + j);
        const float4 mv1 = *(const float4*)(g_hv + 1 * NPLANE + s * 64 + j);
        const float4 mv2 = *(const float4*)(g_hv + 2 * NPLANE + s * 64 + j);

        float4 os, ov0, ov1, ov2;
        if (t < 16) {
            os  = make_float4(ms.x * m1.x, ms.y * m1.y, ms.z * m1.z, ms.w * m1.w);
            ov0 = make_float4(mv0.x * m2.x, mv0.y * m2.y, mv0.z * m2.z, mv0.w * m2.w);
            ov1 = make_float4(mv1.x * m2.x, mv1.y * m2.y, mv1.z * m2.z, mv1.w * m2.w);
            ov2 = make_float4(mv2.x * m2.x, mv2.y * m2.y, mv2.z * m2.z, mv2.w * m2.w);
        } else {
            float tpx = mv0.x * u0 + mv1.x * u1 + mv2.x * u2;
            float tpy = mv0.y * u0 + mv1.y * u1 + mv2.y * u2;
            float tpz = mv0.z * u0 + mv1.z * u1 + mv2.z * u2;
            float tpw = mv0.w * u0 + mv1.w * u1 + mv2.w * u2;
            os  = make_float4(tpx * m1.x, tpy * m1.y, tpz * m1.z, tpw * m1.w);
            ov0 = make_float4(ms.x * y0 * m2.x, ms.y * y0 * m2.y, ms.z * y0 * m2.z, ms.w * y0 * m2.w);
            ov1 = make_float4(ms.x * y1 * m2.x, ms.y * y1 * m2.y, ms.z * y1 * m2.z, ms.w * y1 * m2.w);
            ov2 = make_float4(ms.x * y2 * m2.x, ms.y * y2 * m2.y, ms.z * y2 * m2.z, ms.w * y2 * m2.w);
        }

        if (r != curr) {
            if (curr >= 0) {
                float* base = g_agg + (size_t)curr * 512;
                atomicAdd((float4*)(base + 4 * t),       aS);
                atomicAdd((float4*)(base + 128 + 4 * t), aV0);
                atomicAdd((float4*)(base + 256 + 4 * t), aV1);
                atomicAdd((float4*)(base + 384 + 4 * t), aV2);
            }
            curr = r;
            aS = os; aV0 = ov0; aV1 = ov1; aV2 = ov2;
        } else {
            aS.x += os.x;  aS.y += os.y;  aS.z += os.z;  aS.w += os.w;
            aV0.x += ov0.x; aV0.y += ov0.y; aV0.z += ov0.z; aV0.w += ov0.w;
            aV1.x += ov1.x; aV1.y += ov1.y; aV1.z += ov1.z; aV1.w += ov1.w;
            aV2.x += ov2.x; aV2.y += ov2.y; aV2.z += ov2.z; aV2.w += ov2.w;
        }
    }
    if (curr >= 0) {
        float* base = g_agg + (size_t)curr * 512;
        atomicAdd((float4*)(base + 4 * t),       aS);
        atomicAdd((float4*)(base + 128 + 4 * t), aV0);
        atomicAdd((float4*)(base + 256 + 4 * t), aV1);
        atomicAdd((float4*)(base + 384 + 4 * t), aV2);
    }
}

// =====================================================================
// Kernel 3: node "down" + skip + gate. Warp handles 4 nodes (FFMA2).
// =====================================================================
__global__ void __launch_bounds__(128) k_node_down(
    const float* __restrict__ Wds, const float* __restrict__ Wdv,
    float* __restrict__ out)
{
    __shared__ __align__(16) float agi[4][512][4];
    int w = threadIdx.x >> 5, t = threadIdx.x & 31;
    int n0 = (blockIdx.x * 4 + w) * 4;

#pragma unroll
    for (int nl = 0; nl < 4; nl++) {
        const float4* src = (const float4*)(g_agg + (size_t)(n0 + nl) * 512);
#pragma unroll
        for (int q = 0; q < 4; q++) {
            float4 v = src[t + 32 * q];
            int i = 4 * t + 128 * q;
            agi[w][i + 0][nl] = v.x;
            agi[w][i + 1][nl] = v.y;
            agi[w][i + 2][nl] = v.z;
            agi[w][i + 3][nl] = v.w;
        }
    }
    __syncwarp();

    const float SCALE = INV128F * INVNN;

    u64 accS[4][2] = {};
#pragma unroll 2
    for (int i = 0; i < 128; i++) {
        const u64* xp = (const u64*)agi[w][i];
        u64 x0 = xp[0], x1 = xp[1];
#pragma unroll
        for (int q = 0; q < 4; q++) {
            float ww = __ldg(Wds + i * 128 + t + 32 * q);
            u64 wp = pack2(ww, ww);
            ffma2(accS[q][0], wp, x0);
            ffma2(accS[q][1], wp, x1);
        }
    }

    u64 accV[2][3][2] = {};
#pragma unroll 2
    for (int i = 0; i < 128; i++) {
        float w0 = __ldg(Wdv + i * 64 + t);
        float w1 = __ldg(Wdv + i * 64 + t + 32);
        u64 wp0 = pack2(w0, w0), wp1 = pack2(w1, w1);
#pragma unroll
        for (int c = 0; c < 3; c++) {
            const u64* xp = (const u64*)agi[w][128 + 128 * c + i];
            u64 x0 = xp[0], x1 = xp[1];
            ffma2(accV[0][c][0], wp0, x0);
            ffma2(accV[0][c][1], wp0, x1);
            ffma2(accV[1][c][0], wp1, x0);
            ffma2(accV[1][c][1], wp1, x1);
        }
    }

#pragma unroll
    for (int nl = 0; nl < 4; nl++) {
        int n = n0 + nl;
        int p = nl >> 1, hi = nl & 1;
        const float* sc = g_sc + (size_t)n * 320;
        float ds[4];
#pragma unroll
        for (int q = 0; q < 4; q++) {
            float2 v = unpack2(accS[q][p]);
            ds[q] = (hi ? v.y : v.x) * SCALE + sc[t + 32 * q];
        }
        float g0 = swishf(ds[2]);
        float g1 = swishf(ds[3]);
        float* o = out + (size_t)n * 256;
        o[t]      = swishf(ds[0]);
        o[t + 32] = swishf(ds[1]);
#pragma unroll
        for (int c = 0; c < 3; c++) {
            float2 v0 = unpack2(accV[0][c][p]);
            float2 v1 = unpack2(accV[1][c][p]);
            float d0 = (hi ? v0.y : v0.x) * SCALE + sc[128 + t * 3 + c];
            float d1 = (hi ? v1.y : v1.x) * SCALE + sc[128 + (t + 32) * 3 + c];
            o[64 + t * 3 + c]        = d0 * g0;
            o[64 + (t + 32) * 3 + c] = d1 * g1;
        }
    }
}

// =====================================================================
extern "C" void kernel_launch(void* const* d_in, const int* in_sizes, int n_in,
                              void* d_out, int out_size)
{
    const float* vectors      = (const float*)d_in[0];
    const float* node_scalars = (const float*)d_in[1];
    const float* node_vectors = (const float*)d_in[2];
    const int*   node_specie  = (const int*)  d_in[3];
    const int*   senders      = (const int*)  d_in[4];
    const int*   receivers    = (const int*)  d_in[5];
    const float* W_up_s       = (const float*)d_in[6];
    const float* W_up_v       = (const float*)d_in[7];
    const float* W_skip_s     = (const float*)d_in[8];
    const float* W_skip_v     = (const float*)d_in[9];
    const float* W_mlp1       = (const float*)d_in[10];
    const float* W_mlp2       = (const float*)d_in[11];
    const float* W_mlp3       = (const float*)d_in[12];
    const float* W_down_s     = (const float*)d_in[13];
    const float* W_down_v     = (const float*)d_in[14];
    float* out = (float*)d_out;

    void* aggp = nullptr; cudaGetSymbolAddress(&aggp, g_agg);
    void* cntp = nullptr; cudaGetSymbolAddress(&cntp, g_cnt);
    cudaMemsetAsync(aggp, 0, (size_t)N_NODES * 512 * sizeof(float));
    cudaMemsetAsync(cntp, 0, N_NODES * sizeof(int));

    // receiver-sorted permutation
    k_hist<<<(N_EDGES + 255) / 256, 256>>>(receivers);
    k_scan<<<1, SCAN_T>>>();
    k_scatter<<<(N_EDGES + 255) / 256, 256>>>(receivers);

    // radial-MLP lookup table
    cudaFuncSetAttribute(k_table, cudaFuncAttributeMaxDynamicSharedMemorySize, 20480 * 4);
    k_table<<<TBL / 16, 256, 20480 * 4>>>(W_mlp1, W_mlp2, W_mlp3);

    k_node_up<<<(N_NODES + 7) / 8, 256>>>(node_scalars, node_vectors, node_specie,
                                          W_up_s, W_up_v, W_skip_s, W_skip_v);

    k_edge<<<N_EDGES / (K2W * EPW), 256>>>(vectors, senders, receivers);

    k_node_down<<<N_NODES / 16, 128>>>(W_down_s, W_down_v, out);
}